// round 4
// baseline (speedup 1.0000x reference)
#include <cuda_runtime.h>
#include <math.h>

#define CL   12
#define CH   12
#define CDK  64
#define CDM  768
#define CDFF 3072
#define CV   32128
#define CB   2
#define CS   512
#define CT   512
#define NROWS (CB*CS)
#define NEGV (-1e9f)

// ------------------------- device scratch (static, no allocation) ---------
__device__ __align__(16) float g_x  [NROWS*CDM];
__device__ __align__(16) float g_h  [NROWS*CDM];
__device__ __align__(16) float g_q  [NROWS*CDM];
__device__ __align__(16) float g_k  [NROWS*CDM];
__device__ __align__(16) float g_v  [NROWS*CDM];
__device__ __align__(16) float g_o  [NROWS*CDM];
__device__ __align__(16) float g_mem[NROWS*CDM];
__device__ __align__(16) float g_ff [NROWS*CDFF];
__device__ __align__(16) float g_sc [(size_t)CB*CH*CS*CS];
__device__ __align__(16) float g_bacc[CB*CS];
__device__ __align__(16) float g_pm  [CB*CS];

// ------------------------- rel-position buckets (exact thresholds) --------
__device__ __forceinline__ int bucket_bi(int q, int k) {
    int n = q - k; int ret = 0;
    if (n < 0) { ret = 16; n = -n; }
    if (n < 8) return ret + n;
    int b;
    if      (n < 12) b = 8;
    else if (n < 16) b = 9;
    else if (n < 23) b = 10;
    else if (n < 32) b = 11;
    else if (n < 46) b = 12;
    else if (n < 64) b = 13;
    else if (n < 91) b = 14;
    else             b = 15;
    return ret + b;
}
__device__ __forceinline__ int bucket_uni(int q, int k) {
    int n = q - k; if (n <= 0) return 0;
    if (n < 16) return n;
    if (n < 19)  return 16;
    if (n < 21)  return 17;
    if (n < 24)  return 18;
    if (n < 27)  return 19;
    if (n < 31)  return 20;
    if (n < 35)  return 21;
    if (n < 40)  return 22;
    if (n < 46)  return 23;
    if (n < 52)  return 24;
    if (n < 59)  return 25;
    if (n < 67)  return 26;
    if (n < 77)  return 27;
    if (n < 87)  return 28;
    if (n < 99)  return 29;
    if (n < 113) return 30;
    return 31;
}

// ------------------------- GEMMs ------------------------------------------
// Big: 128x128 tile, BK=8, 256 threads, 8x8 microtile. NT => B is [N,K].
template<bool NT, bool ADD, bool RELU>
__global__ void __launch_bounds__(256) gemm_big(
    const float* __restrict__ A, const float* __restrict__ B,
    float* __restrict__ C, int M, int N, int K)
{
    __shared__ float As[8][128];
    __shared__ float Bs[8][128];
    const int tid = threadIdx.x;
    const int m0 = blockIdx.y * 128;
    const int n0 = blockIdx.x * 128;
    const int arow = tid >> 1;
    const int akq  = (tid & 1) << 2;
    const int bkrow = tid >> 5;
    const int bnq   = (tid & 31) << 2;
    const int tx = tid & 15, ty = tid >> 4;
    float acc[8][8];
#pragma unroll
    for (int i = 0; i < 8; i++)
#pragma unroll
        for (int j = 0; j < 8; j++) acc[i][j] = 0.f;

    const float* Ap = A + (size_t)(m0 + arow) * K + akq;
    const float* Bp = NT ? (B + (size_t)(n0 + arow) * K + akq)
                         : (B + (size_t)bkrow * N + n0 + bnq);
    for (int k0 = 0; k0 < K; k0 += 8) {
        float4 av = *(const float4*)(Ap + k0);
        As[akq+0][arow] = av.x; As[akq+1][arow] = av.y;
        As[akq+2][arow] = av.z; As[akq+3][arow] = av.w;
        if (NT) {
            float4 bv = *(const float4*)(Bp + k0);
            Bs[akq+0][arow] = bv.x; Bs[akq+1][arow] = bv.y;
            Bs[akq+2][arow] = bv.z; Bs[akq+3][arow] = bv.w;
        } else {
            float4 bv = *(const float4*)(Bp + (size_t)k0 * N);
            *(float4*)&Bs[bkrow][bnq] = bv;
        }
        __syncthreads();
#pragma unroll
        for (int kk = 0; kk < 8; kk++) {
            float4 a0 = *(const float4*)&As[kk][ty*4];
            float4 a1 = *(const float4*)&As[kk][64 + ty*4];
            float4 b0 = *(const float4*)&Bs[kk][tx*4];
            float4 b1 = *(const float4*)&Bs[kk][64 + tx*4];
            float a[8] = {a0.x,a0.y,a0.z,a0.w,a1.x,a1.y,a1.z,a1.w};
            float b[8] = {b0.x,b0.y,b0.z,b0.w,b1.x,b1.y,b1.z,b1.w};
#pragma unroll
            for (int i = 0; i < 8; i++)
#pragma unroll
                for (int j = 0; j < 8; j++)
                    acc[i][j] += a[i] * b[j];
        }
        __syncthreads();
    }
#pragma unroll
    for (int i = 0; i < 8; i++) {
        int r = m0 + ((i < 4) ? (ty*4 + i) : (64 + ty*4 + i - 4));
#pragma unroll
        for (int j = 0; j < 8; j++) {
            int c = n0 + ((j < 4) ? (tx*4 + j) : (64 + tx*4 + j - 4));
            float v = acc[i][j];
            if (ADD)  v += C[(size_t)r * N + c];
            if (RELU) v = fmaxf(v, 0.f);
            C[(size_t)r * N + c] = v;
        }
    }
}

// Small: 64x64 tile, BK=16, 256 threads, 4x4 microtile, NN only.
template<bool ADD>
__global__ void __launch_bounds__(256) gemm_small(
    const float* __restrict__ A, const float* __restrict__ B,
    float* __restrict__ C, int M, int N, int K)
{
    __shared__ float As[16][64];
    __shared__ float Bs[16][64];
    const int tid = threadIdx.x;
    const int m0 = blockIdx.y * 64;
    const int n0 = blockIdx.x * 64;
    const int arow = tid >> 2;
    const int akq  = (tid & 3) << 2;
    const int bkrow = tid >> 4;
    const int bnq   = (tid & 15) << 2;
    const int tx = tid & 15, ty = tid >> 4;
    float acc[4][4] = {};
    const float* Ap = A + (size_t)(m0 + arow) * K + akq;
    const float* Bp = B + (size_t)bkrow * N + n0 + bnq;
    for (int k0 = 0; k0 < K; k0 += 16) {
        float4 av = *(const float4*)(Ap + k0);
        As[akq+0][arow] = av.x; As[akq+1][arow] = av.y;
        As[akq+2][arow] = av.z; As[akq+3][arow] = av.w;
        float4 bv = *(const float4*)(Bp + (size_t)k0 * N);
        *(float4*)&Bs[bkrow][bnq] = bv;
        __syncthreads();
#pragma unroll
        for (int kk = 0; kk < 16; kk++) {
            float4 a4 = *(const float4*)&As[kk][ty*4];
            float4 b4 = *(const float4*)&Bs[kk][tx*4];
            float a[4] = {a4.x,a4.y,a4.z,a4.w};
            float b[4] = {b4.x,b4.y,b4.z,b4.w};
#pragma unroll
            for (int i = 0; i < 4; i++)
#pragma unroll
                for (int j = 0; j < 4; j++)
                    acc[i][j] += a[i] * b[j];
        }
        __syncthreads();
    }
#pragma unroll
    for (int i = 0; i < 4; i++) {
        int r = m0 + ty*4 + i;
#pragma unroll
        for (int j = 0; j < 4; j++) {
            int c = n0 + tx*4 + j;
            float v = acc[i][j];
            if (ADD) v += C[(size_t)r * N + c];
            C[(size_t)r * N + c] = v;
        }
    }
}

// ------------------------- attention scores (bias fused on the fly) -------
// MODE 0: encoder self.  MODE 1: decoder self.  MODE 2: decoder cross.
template<int MODE>
__global__ void __launch_bounds__(256) attn_scores(
    const float* __restrict__ Q, const float* __restrict__ Km,
    float* __restrict__ Sc, const float* __restrict__ relb,
    const int* __restrict__ src_len, const int* __restrict__ tgt_len,
    const float* __restrict__ bacc, const float* __restrict__ pmf,
    int enc_layer)
{
    __shared__ float Qt[64][65];
    __shared__ float Kt[64][65];
    const int bh = blockIdx.z, b = bh / CH, hh = bh % CH;
    const int q0 = blockIdx.y * 64, k0 = blockIdx.x * 64;
    const int tid = threadIdx.x;
#pragma unroll
    for (int it = 0; it < 4; it++) {
        int idx = tid + it * 256;
        int r = idx >> 4, cq = (idx & 15) << 2;
        float4 a = *(const float4*)(Q  + (size_t)(b*CS + q0 + r) * CDM + hh*CDK + cq);
        Qt[cq+0][r] = a.x; Qt[cq+1][r] = a.y; Qt[cq+2][r] = a.z; Qt[cq+3][r] = a.w;
        float4 c = *(const float4*)(Km + (size_t)(b*CS + k0 + r) * CDM + hh*CDK + cq);
        Kt[cq+0][r] = c.x; Kt[cq+1][r] = c.y; Kt[cq+2][r] = c.z; Kt[cq+3][r] = c.w;
    }
    __syncthreads();
    const int tx = tid & 15, ty = tid >> 4;
    float acc[4][4] = {};
#pragma unroll 8
    for (int d = 0; d < 64; d++) {
        float a[4], bb[4];
#pragma unroll
        for (int i = 0; i < 4; i++) { a[i] = Qt[d][ty*4+i]; bb[i] = Kt[d][tx*4+i]; }
#pragma unroll
        for (int i = 0; i < 4; i++)
#pragma unroll
            for (int j = 0; j < 4; j++)
                acc[i][j] += a[i] * bb[j];
    }
    const int slen = src_len[b];
#pragma unroll
    for (int i = 0; i < 4; i++) {
        int qg = q0 + ty*4 + i;
#pragma unroll
        for (int j = 0; j < 4; j++) {
            int kg = k0 + tx*4 + j;
            float bias;
            if (MODE == 0) {
                if (enc_layer > 0 && qg == kg) bias = 0.f;
                else {
                    bias = relb[bucket_bi(qg, kg) * CH + hh]
                         + ((kg < slen) ? 0.f : NEGV)
                         + bacc[b*CS + qg] + bacc[b*CS + kg];
                }
            } else if (MODE == 1) {
                float tm;
                if (kg == 0 && qg >= tgt_len[b]) tm = 0.f;
                else tm = ((kg < slen) ? 0.f : NEGV)
                        + (((kg <= qg) && (kg >= qg - 128)) ? 0.f : NEGV);
                bias = relb[bucket_uni(qg, kg) * CH + hh] + tm;
            } else {
                bias = ((kg < slen) ? 0.f : NEGV) + pmf[b*CS + kg];
            }
            Sc[((size_t)bh * CS + qg) * CS + kg] = acc[i][j] + bias;
        }
    }
}

// ------------------------- softmax over rows of length 512 ----------------
__global__ void __launch_bounds__(256) softmax_kernel(float* __restrict__ Sc)
{
    __shared__ float sh[8];
    float* row = Sc + (size_t)blockIdx.x * CS;
    const int t = threadIdx.x;
    float v0 = row[t], v1 = row[t + 256];
    float m = fmaxf(v0, v1);
#pragma unroll
    for (int o = 16; o; o >>= 1) m = fmaxf(m, __shfl_xor_sync(0xffffffffu, m, o));
    if ((t & 31) == 0) sh[t >> 5] = m;
    __syncthreads();
    float bm = sh[t & 7];
#pragma unroll
    for (int o = 4; o; o >>= 1) bm = fmaxf(bm, __shfl_xor_sync(0xffffffffu, bm, o));
    float e0 = expf(v0 - bm), e1 = expf(v1 - bm);
    float s = e0 + e1;
#pragma unroll
    for (int o = 16; o; o >>= 1) s += __shfl_xor_sync(0xffffffffu, s, o);
    __syncthreads();
    if ((t & 31) == 0) sh[t >> 5] = s;
    __syncthreads();
    float ts = sh[t & 7];
#pragma unroll
    for (int o = 4; o; o >>= 1) ts += __shfl_xor_sync(0xffffffffu, ts, o);
    float inv = 1.f / ts;
    row[t] = e0 * inv; row[t + 256] = e1 * inv;
}

// ------------------------- attention P @ V --------------------------------
__global__ void __launch_bounds__(256) attn_av(
    const float* __restrict__ P, const float* __restrict__ V, float* __restrict__ O)
{
    __shared__ float Pt[64][65];
    __shared__ float Vs[64][65];
    const int bh = blockIdx.y, b = bh / CH, hh = bh % CH;
    const int q0 = blockIdx.x * 64;
    const int tid = threadIdx.x;
    const int tx = tid & 15, ty = tid >> 4;
    float acc[4][4] = {};
    for (int k0 = 0; k0 < CS; k0 += 64) {
#pragma unroll
        for (int it = 0; it < 4; it++) {
            int idx = tid + it * 256;
            int r = idx >> 4, cq = (idx & 15) << 2;
            float4 p = *(const float4*)(P + ((size_t)bh * CS + q0 + r) * CS + k0 + cq);
            Pt[cq+0][r] = p.x; Pt[cq+1][r] = p.y; Pt[cq+2][r] = p.z; Pt[cq+3][r] = p.w;
            float4 vv = *(const float4*)(V + (size_t)(b*CS + k0 + r) * CDM + hh*CDK + cq);
            Vs[r][cq+0] = vv.x; Vs[r][cq+1] = vv.y; Vs[r][cq+2] = vv.z; Vs[r][cq+3] = vv.w;
        }
        __syncthreads();
#pragma unroll 8
        for (int kk = 0; kk < 64; kk++) {
            float a[4], bb[4];
#pragma unroll
            for (int i = 0; i < 4; i++) { a[i] = Pt[kk][ty*4+i]; bb[i] = Vs[kk][tx*4+i]; }
#pragma unroll
            for (int i = 0; i < 4; i++)
#pragma unroll
                for (int j = 0; j < 4; j++)
                    acc[i][j] += a[i] * bb[j];
        }
        __syncthreads();
    }
#pragma unroll
    for (int i = 0; i < 4; i++)
#pragma unroll
        for (int j = 0; j < 4; j++)
            O[(size_t)(b*CS + q0 + ty*4 + i) * CDM + hh*CDK + tx*4 + j] = acc[i][j];
}

// ------------------------- RMSNorm (T5) -----------------------------------
__global__ void __launch_bounds__(256) rms_kernel(
    const float* __restrict__ x, const float* __restrict__ w,
    float* __restrict__ out, float scale)
{
    __shared__ float sh[8];
    const int row = blockIdx.x, t = threadIdx.x;
    const float* xr = x + (size_t)row * CDM;
    float v0 = xr[t], v1 = xr[t+256], v2 = xr[t+512];
    float s = v0*v0 + v1*v1 + v2*v2;
#pragma unroll
    for (int o = 16; o; o >>= 1) s += __shfl_xor_sync(0xffffffffu, s, o);
    if ((t & 31) == 0) sh[t >> 5] = s;
    __syncthreads();
    float ts = sh[t & 7];
#pragma unroll
    for (int o = 4; o; o >>= 1) ts += __shfl_xor_sync(0xffffffffu, ts, o);
    float inv = rsqrtf(ts * (1.0f/CDM) + 1e-6f) * scale;
    float* orow = out + (size_t)row * CDM;
    orow[t]     = v0 * inv * w[t];
    orow[t+256] = v1 * inv * w[t+256];
    orow[t+512] = v2 * inv * w[t+512];
}

// ------------------------- embedding gather -------------------------------
__global__ void __launch_bounds__(256) embed_gather(
    const float* __restrict__ embed, const int* __restrict__ tok,
    float* __restrict__ out)
{
    int idx = blockIdx.x * 256 + threadIdx.x;          // 0 .. NROWS*CDM-1
    int r = idx / CDM, c = idx - r * CDM;
    out[idx] = embed[(size_t)tok[r] * CDM + c];
}

__global__ void zero_ch0(float* __restrict__ x)
{
    int r = blockIdx.x * 256 + threadIdx.x;
    if (r < NROWS) x[(size_t)r * CDM] = 0.f;
}

__global__ void init_bacc()
{
    int i = blockIdx.x * 256 + threadIdx.x;
    if (i < CB*CS) g_bacc[i] = 0.f;
}

__global__ void copy_k(const float* __restrict__ src, float* __restrict__ dst)
{
    int i = blockIdx.x * 256 + threadIdx.x;
    dst[i] = src[i];
}

// ------------------------- prune gate -------------------------------------
__global__ void __launch_bounds__(512) gate_kernel(
    const float* __restrict__ x, const float* __restrict__ gumbel,
    const int* __restrict__ src_len, const int* __restrict__ keep,
    float* __restrict__ out_pm, float* __restrict__ out_pp, int layer)
{
    const int b = blockIdx.x, s = threadIdx.x;
    float x0 = x[(size_t)(b*CS + s) * CDM];
    float z = (x0 + gumbel[(b*CL + layer) * CS + s] + 3.0f) * 2.0f; // /TEMP=0.5
    float ls = (z >= 0.f) ? -log1pf(expf(-z)) : (z - log1pf(expf(z)));
    float pm = ls + ((layer > 0) ? g_pm[b*CS + s] : 0.f);
    if (s == keep[b]) pm = 0.f;
    g_pm[b*CS + s] = pm;
    g_bacc[b*CS + s] += pm;
    out_pm[(b*CL + layer) * CS + s] = pm;
    out_pp[(b*CL + layer) * CS + s] = expf(pm * 0.125f) * ((s < src_len[b]) ? 1.f : 0.f);
}

// ------------------------- host orchestration -----------------------------
extern "C" void kernel_launch(void* const* d_in, const int* in_sizes, int n_in,
                              void* d_out, int out_size)
{
    const float* embed      = (const float*)d_in[0];
    const float* enc_ln     = (const float*)d_in[1];
    const float* enc_attn_w = (const float*)d_in[2];
    const float* enc_wi     = (const float*)d_in[3];
    const float* enc_wo     = (const float*)d_in[4];
    const float* enc_relb   = (const float*)d_in[5];
    const float* enc_fln    = (const float*)d_in[6];
    const float* dec_ln     = (const float*)d_in[7];
    const float* dec_self_w = (const float*)d_in[8];
    const float* dec_cross_w= (const float*)d_in[9];
    const float* dec_wi     = (const float*)d_in[10];
    const float* dec_wo     = (const float*)d_in[11];
    const float* dec_relb   = (const float*)d_in[12];
    const float* dec_fln    = (const float*)d_in[13];
    const float* gumbel     = (const float*)d_in[14];
    const int*   src_tok    = (const int*)d_in[15];
    const int*   src_len    = (const int*)d_in[16];
    const int*   tgt_tok    = (const int*)d_in[17];
    const int*   tgt_len    = (const int*)d_in[18];
    const int*   keep       = (const int*)d_in[19];

    float* out = (float*)d_out;
    float* out_mem = out;                          // B*S*DM = 786432
    float* out_pm  = out + (size_t)CB*CS*CDM;      // B*L*S  = 12288
    float* out_pp  = out_pm + (size_t)CB*CL*CS;    // B*L*S  = 12288
    float* out_log = out_pp + (size_t)CB*CL*CS;    // B*T*V

    float *x, *h, *q, *k, *v, *o, *mem, *ff, *sc, *bacc, *pm;
    cudaGetSymbolAddress((void**)&x,   g_x);
    cudaGetSymbolAddress((void**)&h,   g_h);
    cudaGetSymbolAddress((void**)&q,   g_q);
    cudaGetSymbolAddress((void**)&k,   g_k);
    cudaGetSymbolAddress((void**)&v,   g_v);
    cudaGetSymbolAddress((void**)&o,   g_o);
    cudaGetSymbolAddress((void**)&mem, g_mem);
    cudaGetSymbolAddress((void**)&ff,  g_ff);
    cudaGetSymbolAddress((void**)&sc,  g_sc);
    cudaGetSymbolAddress((void**)&bacc,g_bacc);
    cudaGetSymbolAddress((void**)&pm,  g_pm);

    const dim3 gP(CDM/64, NROWS/64);           // projections 64x64
    const dim3 gF1(CDFF/128, NROWS/128);       // ffn1 128x128
    const dim3 gSc(CS/64, CS/64, CB*CH);
    const dim3 gAv(CS/64, CB*CH);
    const int  nSoft = CB*CH*CS;
    const float inv_sqrt_dm = 0.03608439182435161f;  // 768^-0.5

    init_bacc<<<4, 256>>>();
    embed_gather<<<NROWS*CDM/256, 256>>>(embed, src_tok, x);

    // ---------------- encoder ----------------
    for (int i = 0; i < CL; i++) {
        const float* W = enc_attn_w + (size_t)i*4*CDM*CDM;
        zero_ch0<<<4, 256>>>(x);
        rms_kernel<<<NROWS, 256>>>(x, enc_ln + (size_t)(i*2+0)*CDM, h, 1.f);
        gemm_small<false><<<gP, 256>>>(h, W,                 q, NROWS, CDM, CDM);
        gemm_small<false><<<gP, 256>>>(h, W +   CDM*CDM,     k, NROWS, CDM, CDM);
        gemm_small<false><<<gP, 256>>>(h, W + 2*CDM*CDM,     v, NROWS, CDM, CDM);
        attn_scores<0><<<gSc, 256>>>(q, k, sc, enc_relb, src_len, tgt_len,
                                     bacc, pm, i);
        softmax_kernel<<<nSoft, 256>>>(sc);
        attn_av<<<gAv, 256>>>(sc, v, o);
        gemm_small<true><<<gP, 256>>>(o, W + 3*CDM*CDM, x, NROWS, CDM, CDM);
        rms_kernel<<<NROWS, 256>>>(x, enc_ln + (size_t)(i*2+1)*CDM, h, 1.f);
        gemm_big<false,false,true><<<gF1, 256>>>(h, enc_wi + (size_t)i*CDM*CDFF,
                                                 ff, NROWS, CDFF, CDM);
        gemm_small<true><<<gP, 256>>>(ff, enc_wo + (size_t)i*CDFF*CDM,
                                      x, NROWS, CDM, CDFF);
        gate_kernel<<<CB, 512>>>(x, gumbel, src_len, keep, out_pm, out_pp, i);
    }
    rms_kernel<<<NROWS, 256>>>(x, enc_fln, mem, 1.f);
    copy_k<<<NROWS*CDM/256, 256>>>(mem, out_mem);

    // ---------------- decoder ----------------
    embed_gather<<<NROWS*CDM/256, 256>>>(embed, tgt_tok, x);
    for (int i = 0; i < CL; i++) {
        const float* Ws = dec_self_w  + (size_t)i*4*CDM*CDM;
        const float* Wc = dec_cross_w + (size_t)i*4*CDM*CDM;
        // self attention
        rms_kernel<<<NROWS, 256>>>(x, dec_ln + (size_t)(i*3+0)*CDM, h, 1.f);
        gemm_small<false><<<gP, 256>>>(h, Ws,               q, NROWS, CDM, CDM);
        gemm_small<false><<<gP, 256>>>(h, Ws +   CDM*CDM,   k, NROWS, CDM, CDM);
        gemm_small<false><<<gP, 256>>>(h, Ws + 2*CDM*CDM,   v, NROWS, CDM, CDM);
        attn_scores<1><<<gSc, 256>>>(q, k, sc, dec_relb, src_len, tgt_len,
                                     bacc, pm, 0);
        softmax_kernel<<<nSoft, 256>>>(sc);
        attn_av<<<gAv, 256>>>(sc, v, o);
        gemm_small<true><<<gP, 256>>>(o, Ws + 3*CDM*CDM, x, NROWS, CDM, CDM);
        // cross attention
        rms_kernel<<<NROWS, 256>>>(x, dec_ln + (size_t)(i*3+1)*CDM, h, 1.f);
        gemm_small<false><<<gP, 256>>>(h,   Wc,               q, NROWS, CDM, CDM);
        gemm_small<false><<<gP, 256>>>(mem, Wc +   CDM*CDM,   k, NROWS, CDM, CDM);
        gemm_small<false><<<gP, 256>>>(mem, Wc + 2*CDM*CDM,   v, NROWS, CDM, CDM);
        attn_scores<2><<<gSc, 256>>>(q, k, sc, dec_relb, src_len, tgt_len,
                                     bacc, pm, 0);
        softmax_kernel<<<nSoft, 256>>>(sc);
        attn_av<<<gAv, 256>>>(sc, v, o);
        gemm_small<true><<<gP, 256>>>(o, Wc + 3*CDM*CDM, x, NROWS, CDM, CDM);
        // ffn
        rms_kernel<<<NROWS, 256>>>(x, dec_ln + (size_t)(i*3+2)*CDM, h, 1.f);
        gemm_big<false,false,true><<<gF1, 256>>>(h, dec_wi + (size_t)i*CDM*CDFF,
                                                 ff, NROWS, CDFF, CDM);
        gemm_small<true><<<gP, 256>>>(ff, dec_wo + (size_t)i*CDFF*CDM,
                                      x, NROWS, CDM, CDFF);
    }
    rms_kernel<<<NROWS, 256>>>(x, dec_fln, h, inv_sqrt_dm);
    gemm_big<true,false,false><<<dim3(CV/128, NROWS/128), 256>>>(
        h, embed, out_log, NROWS, CV, CDM);
}

// round 5
// speedup vs baseline: 2.1698x; 2.1698x over previous
#include <cuda_runtime.h>
#include <cuda_bf16.h>
#include <math.h>

#define CL   12
#define CH   12
#define CDK  64
#define CDM  768
#define CDFF 3072
#define CV   32128
#define CB   2
#define CS   512
#define CT   512
#define NROWS (CB*CS)
#define NEGV (-1e9f)

// ------------------------- device scratch (static, no allocation) ---------
__device__ __align__(16) float g_x  [NROWS*CDM];
__device__ __align__(16) float g_h  [NROWS*CDM];
__device__ __align__(16) float g_qkv[3*NROWS*CDM];
__device__ __align__(16) float g_o  [NROWS*CDM];
__device__ __align__(16) float g_mem[NROWS*CDM];
__device__ __align__(16) float g_ff [NROWS*CDFF];
__device__ __align__(16) float g_sc [(size_t)CB*CH*CS*CS];
__device__ __align__(16) float g_bacc[CB*CS];
__device__ __align__(16) float g_pm  [CB*CS];

// ------------------------- rel-position buckets (exact thresholds) --------
__device__ __forceinline__ int bucket_bi(int q, int k) {
    int n = q - k; int ret = 0;
    if (n < 0) { ret = 16; n = -n; }
    if (n < 8) return ret + n;
    int b;
    if      (n < 12) b = 8;
    else if (n < 16) b = 9;
    else if (n < 23) b = 10;
    else if (n < 32) b = 11;
    else if (n < 46) b = 12;
    else if (n < 64) b = 13;
    else if (n < 91) b = 14;
    else             b = 15;
    return ret + b;
}
__device__ __forceinline__ int bucket_uni(int q, int k) {
    int n = q - k; if (n <= 0) return 0;
    if (n < 16) return n;
    if (n < 19)  return 16;
    if (n < 21)  return 17;
    if (n < 24)  return 18;
    if (n < 27)  return 19;
    if (n < 31)  return 20;
    if (n < 35)  return 21;
    if (n < 40)  return 22;
    if (n < 46)  return 23;
    if (n < 52)  return 24;
    if (n < 59)  return 25;
    if (n < 67)  return 26;
    if (n < 77)  return 27;
    if (n < 87)  return 28;
    if (n < 99)  return 29;
    if (n < 113) return 30;
    return 31;
}

// ------------------------- tensor-core helpers ----------------------------
__device__ __forceinline__ unsigned smem_u32p(const void* p) {
    return (unsigned)__cvta_generic_to_shared(p);
}
__device__ __forceinline__ void ldsm4(unsigned* r, const void* p) {
    unsigned a = smem_u32p(p);
    asm volatile("ldmatrix.sync.aligned.m8n8.x4.shared.b16 {%0,%1,%2,%3}, [%4];"
        : "=r"(r[0]), "=r"(r[1]), "=r"(r[2]), "=r"(r[3]) : "r"(a));
}
__device__ __forceinline__ void ldsm4t(unsigned* r, const void* p) {
    unsigned a = smem_u32p(p);
    asm volatile("ldmatrix.sync.aligned.m8n8.x4.trans.shared.b16 {%0,%1,%2,%3}, [%4];"
        : "=r"(r[0]), "=r"(r[1]), "=r"(r[2]), "=r"(r[3]) : "r"(a));
}
__device__ __forceinline__ void mma16816(float* c, const unsigned* a, unsigned b0, unsigned b1) {
    asm volatile("mma.sync.aligned.m16n8k16.row.col.f32.bf16.bf16.f32 "
        "{%0,%1,%2,%3}, {%4,%5,%6,%7}, {%8,%9}, {%0,%1,%2,%3};"
        : "+f"(c[0]), "+f"(c[1]), "+f"(c[2]), "+f"(c[3])
        : "r"(a[0]), "r"(a[1]), "r"(a[2]), "r"(a[3]), "r"(b0), "r"(b1));
}
__device__ __forceinline__ void splt(float x, __nv_bfloat16& h, __nv_bfloat16& l) {
    h = __float2bfloat16_rn(x);
    l = __float2bfloat16_rn(x - __bfloat162float(h));
}

// ------------------------- split-bf16 tensor GEMM --------------------------
// C[M,N] = A[M,K] * B  (+C) (ReLU).  A,B,C fp32.  NT: B is [N,K] row-major.
// BM=64, BK=32, 256 threads (8 warps: 4 m-groups x 2 n-groups).
// BATCH: blockIdx.z selects A (z==0 ? A0 : A1), B += z*bStride, C += z*cStride.
template<int BN, bool NT, bool ADD, bool RELU, bool BATCH>
__global__ void __launch_bounds__(256) gemm_tc(
    const float* __restrict__ A0, const float* __restrict__ A1,
    const float* __restrict__ Bb, long bStride,
    float* __restrict__ Cb, long cStride,
    int M, int N, int K)
{
    constexpr int LDA = 40;       // bf16 elems (80B rows: conflict-free LDSM)
    constexpr int LDB = BN + 8;   // 72 or 136 (144B/272B rows)
    constexpr int NT8 = BN / 16;  // n8 tiles per warp (warp covers BN/2 cols)
    constexpr int PB  = BN / 32;  // B-prefetch float4 per thread

    __shared__ __align__(16) __nv_bfloat16 Ah[64*LDA], Al[64*LDA];
    __shared__ __align__(16) __nv_bfloat16 Bh[32*LDB], Bl[32*LDB];

    const int tid  = threadIdx.x;
    const int z    = BATCH ? blockIdx.z : 0;
    const float* A = (BATCH && z > 0) ? A1 : A0;
    const float* B = Bb + (size_t)z * bStride;
    float*       C = Cb + (size_t)z * cStride;
    const int m0 = blockIdx.y * 64;
    const int n0 = blockIdx.x * BN;
    const int nk = K >> 5;

    const int lane = tid & 31, w = tid >> 5;
    const int wm = w & 3, wn = w >> 2;
    const int arow = tid >> 3, ac = (tid & 7) << 2;

    float4 pa[2];
    float4 pb[PB];

    float acc[NT8][4];
#pragma unroll
    for (int i = 0; i < NT8; i++) { acc[i][0]=acc[i][1]=acc[i][2]=acc[i][3]=0.f; }

    auto loadg = [&](int kt) {
#pragma unroll
        for (int it = 0; it < 2; it++)
            pa[it] = *(const float4*)(A + (size_t)(m0 + arow + it*32) * K + kt*32 + ac);
        if (NT) {
#pragma unroll
            for (int it = 0; it < PB; it++) {
                int idx = tid + it*256;
                int n = idx >> 3, kq = (idx & 7) << 2;
                pb[it] = *(const float4*)(B + (size_t)(n0 + n) * K + kt*32 + kq);
            }
        } else {
#pragma unroll
            for (int it = 0; it < PB; it++) {
                int idx = tid + it*256;
                int br = idx / (BN/4), bc = (idx % (BN/4)) * 4;
                pb[it] = *(const float4*)(B + (size_t)(kt*32 + br) * N + n0 + bc);
            }
        }
    };
    auto stores = [&]() {
#pragma unroll
        for (int it = 0; it < 2; it++) {
            int row = arow + it*32;
            splt(pa[it].x, Ah[row*LDA+ac+0], Al[row*LDA+ac+0]);
            splt(pa[it].y, Ah[row*LDA+ac+1], Al[row*LDA+ac+1]);
            splt(pa[it].z, Ah[row*LDA+ac+2], Al[row*LDA+ac+2]);
            splt(pa[it].w, Ah[row*LDA+ac+3], Al[row*LDA+ac+3]);
        }
        if (NT) {
#pragma unroll
            for (int it = 0; it < PB; it++) {
                int idx = tid + it*256;
                int n = idx >> 3, kq = (idx & 7) << 2;
                float xs[4] = {pb[it].x, pb[it].y, pb[it].z, pb[it].w};
#pragma unroll
                for (int j = 0; j < 4; j++)
                    splt(xs[j], Bh[(kq+j)*LDB + n], Bl[(kq+j)*LDB + n]);
            }
        } else {
#pragma unroll
            for (int it = 0; it < PB; it++) {
                int idx = tid + it*256;
                int br = idx / (BN/4), bc = (idx % (BN/4)) * 4;
                splt(pb[it].x, Bh[br*LDB+bc+0], Bl[br*LDB+bc+0]);
                splt(pb[it].y, Bh[br*LDB+bc+1], Bl[br*LDB+bc+1]);
                splt(pb[it].z, Bh[br*LDB+bc+2], Bl[br*LDB+bc+2]);
                splt(pb[it].w, Bh[br*LDB+bc+3], Bl[br*LDB+bc+3]);
            }
        }
    };

    loadg(0);
    stores();
    __syncthreads();

    for (int kt = 0; kt < nk; kt++) {
        const bool more = (kt + 1 < nk);
        if (more) loadg(kt + 1);
#pragma unroll
        for (int kh = 0; kh < 2; kh++) {
            unsigned ah[4], al[4];
            const int aoff = (wm*16 + (lane & 15)) * LDA + kh*16 + ((lane >> 4) << 3);
            ldsm4(ah, &Ah[aoff]);
            ldsm4(al, &Al[aoff]);
            unsigned bh[NT8*2], bl[NT8*2];
#pragma unroll
            for (int t2 = 0; t2 < NT8/2; t2++) {
                const int boff = (kh*16 + (lane & 15)) * LDB
                               + wn*(BN/2) + t2*16 + ((lane >> 4) << 3);
                ldsm4t(&bh[t2*4], &Bh[boff]);
                ldsm4t(&bl[t2*4], &Bl[boff]);
            }
#pragma unroll
            for (int nt = 0; nt < NT8; nt++) mma16816(acc[nt], ah, bh[2*nt], bh[2*nt+1]);
#pragma unroll
            for (int nt = 0; nt < NT8; nt++) mma16816(acc[nt], ah, bl[2*nt], bl[2*nt+1]);
#pragma unroll
            for (int nt = 0; nt < NT8; nt++) mma16816(acc[nt], al, bh[2*nt], bh[2*nt+1]);
        }
        __syncthreads();
        if (more) { stores(); __syncthreads(); }
    }

    // epilogue
    const int g = lane >> 2, qd = lane & 3;
#pragma unroll
    for (int nt = 0; nt < NT8; nt++) {
        const int col = n0 + wn*(BN/2) + nt*8 + qd*2;
        const int r0  = m0 + wm*16 + g;
        size_t i0 = (size_t)r0 * N + col;
        size_t i1 = i0 + (size_t)8 * N;
        float v0 = acc[nt][0], v1 = acc[nt][1], v2 = acc[nt][2], v3 = acc[nt][3];
        if (ADD) { v0 += C[i0]; v1 += C[i0+1]; v2 += C[i1]; v3 += C[i1+1]; }
        if (RELU) { v0 = fmaxf(v0,0.f); v1 = fmaxf(v1,0.f); v2 = fmaxf(v2,0.f); v3 = fmaxf(v3,0.f); }
        C[i0] = v0; C[i0+1] = v1; C[i1] = v2; C[i1+1] = v3;
    }
}

// ------------------------- attention scores (bias fused on the fly) -------
// MODE 0: encoder self.  MODE 1: decoder self.  MODE 2: decoder cross.
template<int MODE>
__global__ void __launch_bounds__(256) attn_scores(
    const float* __restrict__ Q, const float* __restrict__ Km,
    float* __restrict__ Sc, const float* __restrict__ relb,
    const int* __restrict__ src_len, const int* __restrict__ tgt_len,
    const float* __restrict__ bacc, const float* __restrict__ pmf,
    int enc_layer)
{
    __shared__ float Qt[64][65];
    __shared__ float Kt[64][65];
    const int bh = blockIdx.z, b = bh / CH, hh = bh % CH;
    const int q0 = blockIdx.y * 64, k0 = blockIdx.x * 64;
    const int tid = threadIdx.x;
#pragma unroll
    for (int it = 0; it < 4; it++) {
        int idx = tid + it * 256;
        int r = idx >> 4, cq = (idx & 15) << 2;
        float4 a = *(const float4*)(Q  + (size_t)(b*CS + q0 + r) * CDM + hh*CDK + cq);
        Qt[cq+0][r] = a.x; Qt[cq+1][r] = a.y; Qt[cq+2][r] = a.z; Qt[cq+3][r] = a.w;
        float4 c = *(const float4*)(Km + (size_t)(b*CS + k0 + r) * CDM + hh*CDK + cq);
        Kt[cq+0][r] = c.x; Kt[cq+1][r] = c.y; Kt[cq+2][r] = c.z; Kt[cq+3][r] = c.w;
    }
    __syncthreads();
    const int tx = tid & 15, ty = tid >> 4;
    float acc[4][4] = {};
#pragma unroll 8
    for (int d = 0; d < 64; d++) {
        float a[4], bb[4];
#pragma unroll
        for (int i = 0; i < 4; i++) { a[i] = Qt[d][ty*4+i]; bb[i] = Kt[d][tx*4+i]; }
#pragma unroll
        for (int i = 0; i < 4; i++)
#pragma unroll
            for (int j = 0; j < 4; j++)
                acc[i][j] += a[i] * bb[j];
    }
    const int slen = src_len[b];
#pragma unroll
    for (int i = 0; i < 4; i++) {
        int qg = q0 + ty*4 + i;
#pragma unroll
        for (int j = 0; j < 4; j++) {
            int kg = k0 + tx*4 + j;
            float bias;
            if (MODE == 0) {
                if (enc_layer > 0 && qg == kg) bias = 0.f;
                else {
                    bias = relb[bucket_bi(qg, kg) * CH + hh]
                         + ((kg < slen) ? 0.f : NEGV)
                         + bacc[b*CS + qg] + bacc[b*CS + kg];
                }
            } else if (MODE == 1) {
                float tm;
                if (kg == 0 && qg >= tgt_len[b]) tm = 0.f;
                else tm = ((kg < slen) ? 0.f : NEGV)
                        + (((kg <= qg) && (kg >= qg - 128)) ? 0.f : NEGV);
                bias = relb[bucket_uni(qg, kg) * CH + hh] + tm;
            } else {
                bias = ((kg < slen) ? 0.f : NEGV) + pmf[b*CS + kg];
            }
            Sc[((size_t)bh * CS + qg) * CS + kg] = acc[i][j] + bias;
        }
    }
}

// ------------------------- softmax over rows of length 512 ----------------
__global__ void __launch_bounds__(256) softmax_kernel(float* __restrict__ Sc)
{
    __shared__ float sh[8];
    float* row = Sc + (size_t)blockIdx.x * CS;
    const int t = threadIdx.x;
    float v0 = row[t], v1 = row[t + 256];
    float m = fmaxf(v0, v1);
#pragma unroll
    for (int o = 16; o; o >>= 1) m = fmaxf(m, __shfl_xor_sync(0xffffffffu, m, o));
    if ((t & 31) == 0) sh[t >> 5] = m;
    __syncthreads();
    float bm = sh[t & 7];
#pragma unroll
    for (int o = 4; o; o >>= 1) bm = fmaxf(bm, __shfl_xor_sync(0xffffffffu, bm, o));
    float e0 = expf(v0 - bm), e1 = expf(v1 - bm);
    float s = e0 + e1;
#pragma unroll
    for (int o = 16; o; o >>= 1) s += __shfl_xor_sync(0xffffffffu, s, o);
    __syncthreads();
    if ((t & 31) == 0) sh[t >> 5] = s;
    __syncthreads();
    float ts = sh[t & 7];
#pragma unroll
    for (int o = 4; o; o >>= 1) ts += __shfl_xor_sync(0xffffffffu, ts, o);
    float inv = 1.f / ts;
    row[t] = e0 * inv; row[t + 256] = e1 * inv;
}

// ------------------------- attention P @ V --------------------------------
__global__ void __launch_bounds__(256) attn_av(
    const float* __restrict__ P, const float* __restrict__ V, float* __restrict__ O)
{
    __shared__ float Pt[64][65];
    __shared__ float Vs[64][65];
    const int bh = blockIdx.y, b = bh / CH, hh = bh % CH;
    const int q0 = blockIdx.x * 64;
    const int tid = threadIdx.x;
    const int tx = tid & 15, ty = tid >> 4;
    float acc[4][4] = {};
    for (int k0 = 0; k0 < CS; k0 += 64) {
#pragma unroll
        for (int it = 0; it < 4; it++) {
            int idx = tid + it * 256;
            int r = idx >> 4, cq = (idx & 15) << 2;
            float4 p = *(const float4*)(P + ((size_t)bh * CS + q0 + r) * CS + k0 + cq);
            Pt[cq+0][r] = p.x; Pt[cq+1][r] = p.y; Pt[cq+2][r] = p.z; Pt[cq+3][r] = p.w;
            float4 vv = *(const float4*)(V + (size_t)(b*CS + k0 + r) * CDM + hh*CDK + cq);
            Vs[r][cq+0] = vv.x; Vs[r][cq+1] = vv.y; Vs[r][cq+2] = vv.z; Vs[r][cq+3] = vv.w;
        }
        __syncthreads();
#pragma unroll 8
        for (int kk = 0; kk < 64; kk++) {
            float a[4], bb[4];
#pragma unroll
            for (int i = 0; i < 4; i++) { a[i] = Pt[kk][ty*4+i]; bb[i] = Vs[kk][tx*4+i]; }
#pragma unroll
            for (int i = 0; i < 4; i++)
#pragma unroll
                for (int j = 0; j < 4; j++)
                    acc[i][j] += a[i] * bb[j];
        }
        __syncthreads();
    }
#pragma unroll
    for (int i = 0; i < 4; i++)
#pragma unroll
        for (int j = 0; j < 4; j++)
            O[(size_t)(b*CS + q0 + ty*4 + i) * CDM + hh*CDK + tx*4 + j] = acc[i][j];
}

// ------------------------- RMSNorm (T5) -----------------------------------
__global__ void __launch_bounds__(256) rms_kernel(
    const float* __restrict__ x, const float* __restrict__ w,
    float* __restrict__ out, float scale)
{
    __shared__ float sh[8];
    const int row = blockIdx.x, t = threadIdx.x;
    const float* xr = x + (size_t)row * CDM;
    float v0 = xr[t], v1 = xr[t+256], v2 = xr[t+512];
    float s = v0*v0 + v1*v1 + v2*v2;
#pragma unroll
    for (int o = 16; o; o >>= 1) s += __shfl_xor_sync(0xffffffffu, s, o);
    if ((t & 31) == 0) sh[t >> 5] = s;
    __syncthreads();
    float ts = sh[t & 7];
#pragma unroll
    for (int o = 4; o; o >>= 1) ts += __shfl_xor_sync(0xffffffffu, ts, o);
    float inv = rsqrtf(ts * (1.0f/CDM) + 1e-6f) * scale;
    float* orow = out + (size_t)row * CDM;
    orow[t]     = v0 * inv * w[t];
    orow[t+256] = v1 * inv * w[t+256];
    orow[t+512] = v2 * inv * w[t+512];
}

// ------------------------- elementwise helpers ----------------------------
__global__ void __launch_bounds__(256) embed_gather(
    const float* __restrict__ embed, const int* __restrict__ tok,
    float* __restrict__ out)
{
    int idx = blockIdx.x * 256 + threadIdx.x;
    int r = idx / CDM, c = idx - r * CDM;
    out[idx] = embed[(size_t)tok[r] * CDM + c];
}

__global__ void zero_ch0(float* __restrict__ x)
{
    int r = blockIdx.x * 256 + threadIdx.x;
    if (r < NROWS) x[(size_t)r * CDM] = 0.f;
}

__global__ void init_bacc()
{
    int i = blockIdx.x * 256 + threadIdx.x;
    if (i < CB*CS) g_bacc[i] = 0.f;
}

__global__ void copy_k(const float* __restrict__ src, float* __restrict__ dst)
{
    int i = blockIdx.x * 256 + threadIdx.x;
    dst[i] = src[i];
}

// ------------------------- prune gate -------------------------------------
__global__ void __launch_bounds__(512) gate_kernel(
    const float* __restrict__ x, const float* __restrict__ gumbel,
    const int* __restrict__ src_len, const int* __restrict__ keep,
    float* __restrict__ out_pm, float* __restrict__ out_pp, int layer)
{
    const int b = blockIdx.x, s = threadIdx.x;
    float x0 = x[(size_t)(b*CS + s) * CDM];
    float z = (x0 + gumbel[(b*CL + layer) * CS + s] + 3.0f) * 2.0f; // /TEMP=0.5
    float ls = (z >= 0.f) ? -log1pf(expf(-z)) : (z - log1pf(expf(z)));
    float pm = ls + ((layer > 0) ? g_pm[b*CS + s] : 0.f);
    if (s == keep[b]) pm = 0.f;
    g_pm[b*CS + s] = pm;
    g_bacc[b*CS + s] += pm;
    out_pm[(b*CL + layer) * CS + s] = pm;
    out_pp[(b*CL + layer) * CS + s] = expf(pm * 0.125f) * ((s < src_len[b]) ? 1.f : 0.f);
}

// ------------------------- host orchestration -----------------------------
extern "C" void kernel_launch(void* const* d_in, const int* in_sizes, int n_in,
                              void* d_out, int out_size)
{
    const float* embed      = (const float*)d_in[0];
    const float* enc_ln     = (const float*)d_in[1];
    const float* enc_attn_w = (const float*)d_in[2];
    const float* enc_wi     = (const float*)d_in[3];
    const float* enc_wo     = (const float*)d_in[4];
    const float* enc_relb   = (const float*)d_in[5];
    const float* enc_fln    = (const float*)d_in[6];
    const float* dec_ln     = (const float*)d_in[7];
    const float* dec_self_w = (const float*)d_in[8];
    const float* dec_cross_w= (const float*)d_in[9];
    const float* dec_wi     = (const float*)d_in[10];
    const float* dec_wo     = (const float*)d_in[11];
    const float* dec_relb   = (const float*)d_in[12];
    const float* dec_fln    = (const float*)d_in[13];
    const float* gumbel     = (const float*)d_in[14];
    const int*   src_tok    = (const int*)d_in[15];
    const int*   src_len    = (const int*)d_in[16];
    const int*   tgt_tok    = (const int*)d_in[17];
    const int*   tgt_len    = (const int*)d_in[18];
    const int*   keep       = (const int*)d_in[19];

    float* out = (float*)d_out;
    float* out_mem = out;                          // B*S*DM
    float* out_pm  = out + (size_t)CB*CS*CDM;      // B*L*S
    float* out_pp  = out_pm + (size_t)CB*CL*CS;    // B*L*S
    float* out_log = out_pp + (size_t)CB*CL*CS;    // B*T*V

    float *x, *h, *qkv, *o, *mem, *ff, *sc, *bacc, *pm;
    cudaGetSymbolAddress((void**)&x,   g_x);
    cudaGetSymbolAddress((void**)&h,   g_h);
    cudaGetSymbolAddress((void**)&qkv, g_qkv);
    cudaGetSymbolAddress((void**)&o,   g_o);
    cudaGetSymbolAddress((void**)&mem, g_mem);
    cudaGetSymbolAddress((void**)&ff,  g_ff);
    cudaGetSymbolAddress((void**)&sc,  g_sc);
    cudaGetSymbolAddress((void**)&bacc,g_bacc);
    cudaGetSymbolAddress((void**)&pm,  g_pm);

    float* q = qkv;
    float* k = qkv + (size_t)NROWS*CDM;
    float* v = qkv + (size_t)2*NROWS*CDM;
    const long QS = (long)NROWS*CDM;
    const long WS = (long)CDM*CDM;

    const dim3 gQKV(CDM/64, NROWS/64, 3);      // batched q,k,v
    const dim3 gPrj(CDM/64, NROWS/64);         // 64-wide N GEMMs
    const dim3 gWi (CDFF/128, NROWS/64);       // ffn up
    const dim3 gLg (CV/128, NROWS/64);         // logits
    const dim3 gSc(CS/64, CS/64, CB*CH);
    const dim3 gAv(CS/64, CB*CH);
    const int  nSoft = CB*CH*CS;
    const float inv_sqrt_dm = 0.03608439182435161f;  // 768^-0.5

    init_bacc<<<4, 256>>>();
    embed_gather<<<NROWS*CDM/256, 256>>>(embed, src_tok, x);

    // ---------------- encoder ----------------
    for (int i = 0; i < CL; i++) {
        const float* W = enc_attn_w + (size_t)i*4*CDM*CDM;
        zero_ch0<<<4, 256>>>(x);
        rms_kernel<<<NROWS, 256>>>(x, enc_ln + (size_t)(i*2+0)*CDM, h, 1.f);
        gemm_tc<64,false,false,false,true><<<gQKV, 256>>>(
            h, h, W, WS, qkv, QS, NROWS, CDM, CDM);
        attn_scores<0><<<gSc, 256>>>(q, k, sc, enc_relb, src_len, tgt_len, bacc, pm, i);
        softmax_kernel<<<nSoft, 256>>>(sc);
        attn_av<<<gAv, 256>>>(sc, v, o);
        gemm_tc<64,false,true,false,false><<<gPrj, 256>>>(
            o, o, W + 3*WS, 0, x, 0, NROWS, CDM, CDM);
        rms_kernel<<<NROWS, 256>>>(x, enc_ln + (size_t)(i*2+1)*CDM, h, 1.f);
        gemm_tc<128,false,false,true,false><<<gWi, 256>>>(
            h, h, enc_wi + (size_t)i*CDM*CDFF, 0, ff, 0, NROWS, CDFF, CDM);
        gemm_tc<64,false,true,false,false><<<gPrj, 256>>>(
            ff, ff, enc_wo + (size_t)i*CDFF*CDM, 0, x, 0, NROWS, CDM, CDFF);
        gate_kernel<<<CB, 512>>>(x, gumbel, src_len, keep, out_pm, out_pp, i);
    }
    rms_kernel<<<NROWS, 256>>>(x, enc_fln, mem, 1.f);
    copy_k<<<NROWS*CDM/256, 256>>>(mem, out_mem);

    // ---------------- decoder ----------------
    embed_gather<<<NROWS*CDM/256, 256>>>(embed, tgt_tok, x);
    for (int i = 0; i < CL; i++) {
        const float* Ws = dec_self_w  + (size_t)i*4*CDM*CDM;
        const float* Wc = dec_cross_w + (size_t)i*4*CDM*CDM;
        // self attention
        rms_kernel<<<NROWS, 256>>>(x, dec_ln + (size_t)(i*3+0)*CDM, h, 1.f);
        gemm_tc<64,false,false,false,true><<<gQKV, 256>>>(
            h, h, Ws, WS, qkv, QS, NROWS, CDM, CDM);
        attn_scores<1><<<gSc, 256>>>(q, k, sc, dec_relb, src_len, tgt_len, bacc, pm, 0);
        softmax_kernel<<<nSoft, 256>>>(sc);
        attn_av<<<gAv, 256>>>(sc, v, o);
        gemm_tc<64,false,true,false,false><<<gPrj, 256>>>(
            o, o, Ws + 3*WS, 0, x, 0, NROWS, CDM, CDM);
        // cross attention (q from h, k/v from mem)
        rms_kernel<<<NROWS, 256>>>(x, dec_ln + (size_t)(i*3+1)*CDM, h, 1.f);
        gemm_tc<64,false,false,false,true><<<gQKV, 256>>>(
            h, mem, Wc, WS, qkv, QS, NROWS, CDM, CDM);
        attn_scores<2><<<gSc, 256>>>(q, k, sc, dec_relb, src_len, tgt_len, bacc, pm, 0);
        softmax_kernel<<<nSoft, 256>>>(sc);
        attn_av<<<gAv, 256>>>(sc, v, o);
        gemm_tc<64,false,true,false,false><<<gPrj, 256>>>(
            o, o, Wc + 3*WS, 0, x, 0, NROWS, CDM, CDM);
        // ffn
        rms_kernel<<<NROWS, 256>>>(x, dec_ln + (size_t)(i*3+2)*CDM, h, 1.f);
        gemm_tc<128,false,false,true,false><<<gWi, 256>>>(
            h, h, dec_wi + (size_t)i*CDM*CDFF, 0, ff, 0, NROWS, CDFF, CDM);
        gemm_tc<64,false,true,false,false><<<gPrj, 256>>>(
            ff, ff, dec_wo + (size_t)i*CDFF*CDM, 0, x, 0, NROWS, CDM, CDFF);
    }
    rms_kernel<<<NROWS, 256>>>(x, dec_fln, h, inv_sqrt_dm);
    gemm_tc<128,true,false,false,false><<<gLg, 256>>>(
        h, h, embed, 0, out_log, 0, NROWS, CV, CDM);
}

// round 6
// speedup vs baseline: 2.4631x; 1.1352x over previous
#include <cuda_runtime.h>
#include <cuda_bf16.h>
#include <math.h>

#define CL   12
#define CH   12
#define CDK  64
#define CDM  768
#define CDFF 3072
#define CV   32128
#define CB   2
#define CS   512
#define CT   512
#define NROWS (CB*CS)
#define NEGV (-1e9f)

// ------------------------- device scratch (static, no allocation) ---------
__device__ __align__(16) float g_x  [NROWS*CDM];
__device__ __align__(16) float g_h  [NROWS*CDM];
__device__ __align__(16) float g_qkv[3*NROWS*CDM];
__device__ __align__(16) float g_o  [NROWS*CDM];
__device__ __align__(16) float g_mem[NROWS*CDM];
__device__ __align__(16) float g_ff [NROWS*CDFF];
__device__ __align__(16) float g_sc [(size_t)CB*CH*CS*CS];
__device__ __align__(16) float g_bacc[CB*CS];
__device__ __align__(16) float g_pm  [CB*CS];

// ------------------------- rel-position buckets (exact thresholds) --------
__device__ __forceinline__ int bucket_bi(int q, int k) {
    int n = q - k; int ret = 0;
    if (n < 0) { ret = 16; n = -n; }
    if (n < 8) return ret + n;
    int b;
    if      (n < 12) b = 8;
    else if (n < 16) b = 9;
    else if (n < 23) b = 10;
    else if (n < 32) b = 11;
    else if (n < 46) b = 12;
    else if (n < 64) b = 13;
    else if (n < 91) b = 14;
    else             b = 15;
    return ret + b;
}
__device__ __forceinline__ int bucket_uni(int q, int k) {
    int n = q - k; if (n <= 0) return 0;
    if (n < 16) return n;
    if (n < 19)  return 16;
    if (n < 21)  return 17;
    if (n < 24)  return 18;
    if (n < 27)  return 19;
    if (n < 31)  return 20;
    if (n < 35)  return 21;
    if (n < 40)  return 22;
    if (n < 46)  return 23;
    if (n < 52)  return 24;
    if (n < 59)  return 25;
    if (n < 67)  return 26;
    if (n < 77)  return 27;
    if (n < 87)  return 28;
    if (n < 99)  return 29;
    if (n < 113) return 30;
    return 31;
}

// ------------------------- tensor-core helpers ----------------------------
__device__ __forceinline__ unsigned smem_u32p(const void* p) {
    return (unsigned)__cvta_generic_to_shared(p);
}
__device__ __forceinline__ void ldsm4(unsigned* r, const void* p) {
    unsigned a = smem_u32p(p);
    asm volatile("ldmatrix.sync.aligned.m8n8.x4.shared.b16 {%0,%1,%2,%3}, [%4];"
        : "=r"(r[0]), "=r"(r[1]), "=r"(r[2]), "=r"(r[3]) : "r"(a));
}
__device__ __forceinline__ void ldsm4t(unsigned* r, const void* p) {
    unsigned a = smem_u32p(p);
    asm volatile("ldmatrix.sync.aligned.m8n8.x4.trans.shared.b16 {%0,%1,%2,%3}, [%4];"
        : "=r"(r[0]), "=r"(r[1]), "=r"(r[2]), "=r"(r[3]) : "r"(a));
}
__device__ __forceinline__ void mma16816(float* c, const unsigned* a, unsigned b0, unsigned b1) {
    asm volatile("mma.sync.aligned.m16n8k16.row.col.f32.bf16.bf16.f32 "
        "{%0,%1,%2,%3}, {%4,%5,%6,%7}, {%8,%9}, {%0,%1,%2,%3};"
        : "+f"(c[0]), "+f"(c[1]), "+f"(c[2]), "+f"(c[3])
        : "r"(a[0]), "r"(a[1]), "r"(a[2]), "r"(a[3]), "r"(b0), "r"(b1));
}
__device__ __forceinline__ void splt(float x, __nv_bfloat16& h, __nv_bfloat16& l) {
    h = __float2bfloat16_rn(x);
    l = __float2bfloat16_rn(x - __bfloat162float(h));
}

// ------------------------- split-bf16 tensor GEMM --------------------------
// C[M,N] = A[M,K] * B  (+C) (ReLU).  A,B,C fp32.  NT: B is [N,K] row-major.
// BM=64, BK=32, 256 threads (8 warps: 4 m-groups x 2 n-groups).
template<int BN, bool NT, bool ADD, bool RELU, bool BATCH>
__global__ void __launch_bounds__(256) gemm_tc(
    const float* __restrict__ A0, const float* __restrict__ A1,
    const float* __restrict__ Bb, long bStride,
    float* __restrict__ Cb, long cStride,
    int M, int N, int K)
{
    constexpr int LDA = 40;
    constexpr int LDB = BN + 8;
    constexpr int NT8 = BN / 16;
    constexpr int PB  = BN / 32;

    __shared__ __align__(16) __nv_bfloat16 Ah[64*LDA], Al[64*LDA];
    __shared__ __align__(16) __nv_bfloat16 Bh[32*LDB], Bl[32*LDB];

    const int tid  = threadIdx.x;
    const int z    = BATCH ? blockIdx.z : 0;
    const float* A = (BATCH && z > 0) ? A1 : A0;
    const float* B = Bb + (size_t)z * bStride;
    float*       C = Cb + (size_t)z * cStride;
    const int m0 = blockIdx.y * 64;
    const int n0 = blockIdx.x * BN;
    const int nk = K >> 5;

    const int lane = tid & 31, w = tid >> 5;
    const int wm = w & 3, wn = w >> 2;
    const int arow = tid >> 3, ac = (tid & 7) << 2;

    float4 pa[2];
    float4 pb[PB];

    float acc[NT8][4];
#pragma unroll
    for (int i = 0; i < NT8; i++) { acc[i][0]=acc[i][1]=acc[i][2]=acc[i][3]=0.f; }

    auto loadg = [&](int kt) {
#pragma unroll
        for (int it = 0; it < 2; it++)
            pa[it] = *(const float4*)(A + (size_t)(m0 + arow + it*32) * K + kt*32 + ac);
        if (NT) {
#pragma unroll
            for (int it = 0; it < PB; it++) {
                int idx = tid + it*256;
                int n = idx >> 3, kq = (idx & 7) << 2;
                pb[it] = *(const float4*)(B + (size_t)(n0 + n) * K + kt*32 + kq);
            }
        } else {
#pragma unroll
            for (int it = 0; it < PB; it++) {
                int idx = tid + it*256;
                int br = idx / (BN/4), bc = (idx % (BN/4)) * 4;
                pb[it] = *(const float4*)(B + (size_t)(kt*32 + br) * N + n0 + bc);
            }
        }
    };
    auto stores = [&]() {
#pragma unroll
        for (int it = 0; it < 2; it++) {
            int row = arow + it*32;
            splt(pa[it].x, Ah[row*LDA+ac+0], Al[row*LDA+ac+0]);
            splt(pa[it].y, Ah[row*LDA+ac+1], Al[row*LDA+ac+1]);
            splt(pa[it].z, Ah[row*LDA+ac+2], Al[row*LDA+ac+2]);
            splt(pa[it].w, Ah[row*LDA+ac+3], Al[row*LDA+ac+3]);
        }
        if (NT) {
#pragma unroll
            for (int it = 0; it < PB; it++) {
                int idx = tid + it*256;
                int n = idx >> 3, kq = (idx & 7) << 2;
                float xs[4] = {pb[it].x, pb[it].y, pb[it].z, pb[it].w};
#pragma unroll
                for (int j = 0; j < 4; j++)
                    splt(xs[j], Bh[(kq+j)*LDB + n], Bl[(kq+j)*LDB + n]);
            }
        } else {
#pragma unroll
            for (int it = 0; it < PB; it++) {
                int idx = tid + it*256;
                int br = idx / (BN/4), bc = (idx % (BN/4)) * 4;
                splt(pb[it].x, Bh[br*LDB+bc+0], Bl[br*LDB+bc+0]);
                splt(pb[it].y, Bh[br*LDB+bc+1], Bl[br*LDB+bc+1]);
                splt(pb[it].z, Bh[br*LDB+bc+2], Bl[br*LDB+bc+2]);
                splt(pb[it].w, Bh[br*LDB+bc+3], Bl[br*LDB+bc+3]);
            }
        }
    };

    loadg(0);
    stores();
    __syncthreads();

    for (int kt = 0; kt < nk; kt++) {
        const bool more = (kt + 1 < nk);
        if (more) loadg(kt + 1);
#pragma unroll
        for (int kh = 0; kh < 2; kh++) {
            unsigned ah[4], al[4];
            const int aoff = (wm*16 + (lane & 15)) * LDA + kh*16 + ((lane >> 4) << 3);
            ldsm4(ah, &Ah[aoff]);
            ldsm4(al, &Al[aoff]);
            unsigned bh[NT8*2], bl[NT8*2];
#pragma unroll
            for (int t2 = 0; t2 < NT8/2; t2++) {
                const int boff = (kh*16 + (lane & 15)) * LDB
                               + wn*(BN/2) + t2*16 + ((lane >> 4) << 3);
                ldsm4t(&bh[t2*4], &Bh[boff]);
                ldsm4t(&bl[t2*4], &Bl[boff]);
            }
#pragma unroll
            for (int nt = 0; nt < NT8; nt++) mma16816(acc[nt], ah, bh[2*nt], bh[2*nt+1]);
#pragma unroll
            for (int nt = 0; nt < NT8; nt++) mma16816(acc[nt], ah, bl[2*nt], bl[2*nt+1]);
#pragma unroll
            for (int nt = 0; nt < NT8; nt++) mma16816(acc[nt], al, bh[2*nt], bh[2*nt+1]);
        }
        __syncthreads();
        if (more) { stores(); __syncthreads(); }
    }

    const int g = lane >> 2, qd = lane & 3;
#pragma unroll
    for (int nt = 0; nt < NT8; nt++) {
        const int col = n0 + wn*(BN/2) + nt*8 + qd*2;
        const int r0  = m0 + wm*16 + g;
        size_t i0 = (size_t)r0 * N + col;
        size_t i1 = i0 + (size_t)8 * N;
        float v0 = acc[nt][0], v1 = acc[nt][1], v2 = acc[nt][2], v3 = acc[nt][3];
        if (ADD) { v0 += C[i0]; v1 += C[i0+1]; v2 += C[i1]; v3 += C[i1+1]; }
        if (RELU) { v0 = fmaxf(v0,0.f); v1 = fmaxf(v1,0.f); v2 = fmaxf(v2,0.f); v3 = fmaxf(v3,0.f); }
        C[i0] = v0; C[i0+1] = v1; C[i1] = v2; C[i1+1] = v3;
    }
}

// ------------------------- bias (shared by score kernels) ------------------
template<int MODE>
__device__ __forceinline__ float score_bias(
    int qg, int kg, int hh, int slen, int tlen,
    const float* __restrict__ relb,
    const float* __restrict__ bacc, const float* __restrict__ pmf,
    int bOff, int enc_layer)
{
    if (MODE == 0) {
        if (enc_layer > 0 && qg == kg) return 0.f;
        return relb[bucket_bi(qg, kg) * CH + hh]
             + ((kg < slen) ? 0.f : NEGV)
             + bacc[bOff + qg] + bacc[bOff + kg];
    } else if (MODE == 1) {
        float tm;
        if (kg == 0 && qg >= tlen) tm = 0.f;
        else tm = ((kg < slen) ? 0.f : NEGV)
                + (((kg <= qg) && (kg >= qg - 128)) ? 0.f : NEGV);
        return relb[bucket_uni(qg, kg) * CH + hh] + tm;
    } else {
        return ((kg < slen) ? 0.f : NEGV) + pmf[bOff + kg];
    }
}

// ------------------------- tensor-core attention scores -------------------
// Per CTA: 64 q x 128 k tile for one (b,h). Q,K fp32 -> split bf16, 3-pass MMA.
template<int MODE>
__global__ void __launch_bounds__(256) scores_tc(
    const float* __restrict__ Q, const float* __restrict__ Km,
    float* __restrict__ Sc, const float* __restrict__ relb,
    const int* __restrict__ src_len, const int* __restrict__ tgt_len,
    const float* __restrict__ bacc, const float* __restrict__ pmf,
    int enc_layer)
{
    constexpr int LDA = 72, LDB = 136;
    __shared__ __align__(16) __nv_bfloat16 Ah[64*LDA], Al[64*LDA];
    __shared__ __align__(16) __nv_bfloat16 Bh[64*LDB], Bl[64*LDB];

    const int bh = blockIdx.z, b = bh / CH, hh = bh % CH;
    const int q0 = blockIdx.y * 64, k0 = blockIdx.x * 128;
    const int tid = threadIdx.x;
    const int lane = tid & 31, w = tid >> 5;
    const int wm = w & 3, wn = w >> 2;

    // load Q tile 64x64 (4 float4/thread)
#pragma unroll
    for (int it = 0; it < 4; it++) {
        int idx = tid + it*256;
        int row = idx >> 4, c = (idx & 15) << 2;
        float4 a = *(const float4*)(Q + (size_t)(b*CS + q0 + row) * CDM + hh*CDK + c);
        splt(a.x, Ah[row*LDA+c+0], Al[row*LDA+c+0]);
        splt(a.y, Ah[row*LDA+c+1], Al[row*LDA+c+1]);
        splt(a.z, Ah[row*LDA+c+2], Al[row*LDA+c+2]);
        splt(a.w, Ah[row*LDA+c+3], Al[row*LDA+c+3]);
    }
    // load K tile 128x64, store transposed [d][tok] (8 float4/thread)
#pragma unroll
    for (int it = 0; it < 8; it++) {
        int idx = tid + it*256;
        int n = idx >> 4, c = (idx & 15) << 2;
        float4 kv = *(const float4*)(Km + (size_t)(b*CS + k0 + n) * CDM + hh*CDK + c);
        splt(kv.x, Bh[(c+0)*LDB + n], Bl[(c+0)*LDB + n]);
        splt(kv.y, Bh[(c+1)*LDB + n], Bl[(c+1)*LDB + n]);
        splt(kv.z, Bh[(c+2)*LDB + n], Bl[(c+2)*LDB + n]);
        splt(kv.w, Bh[(c+3)*LDB + n], Bl[(c+3)*LDB + n]);
    }
    __syncthreads();

    float acc[8][4];
#pragma unroll
    for (int i = 0; i < 8; i++) { acc[i][0]=acc[i][1]=acc[i][2]=acc[i][3]=0.f; }

#pragma unroll
    for (int kh = 0; kh < 4; kh++) {
        unsigned ah[4], al[4];
        const int aoff = (wm*16 + (lane & 15)) * LDA + kh*16 + ((lane >> 4) << 3);
        ldsm4(ah, &Ah[aoff]);
        ldsm4(al, &Al[aoff]);
        unsigned bhf[16], blf[16];
#pragma unroll
        for (int t2 = 0; t2 < 4; t2++) {
            const int boff = (kh*16 + (lane & 15)) * LDB
                           + wn*64 + t2*16 + ((lane >> 4) << 3);
            ldsm4t(&bhf[t2*4], &Bh[boff]);
            ldsm4t(&blf[t2*4], &Bl[boff]);
        }
#pragma unroll
        for (int nt = 0; nt < 8; nt++) mma16816(acc[nt], ah, bhf[2*nt], bhf[2*nt+1]);
#pragma unroll
        for (int nt = 0; nt < 8; nt++) mma16816(acc[nt], ah, blf[2*nt], blf[2*nt+1]);
#pragma unroll
        for (int nt = 0; nt < 8; nt++) mma16816(acc[nt], al, bhf[2*nt], bhf[2*nt+1]);
    }

    const int slen = src_len[b];
    const int tlen = (MODE == 1) ? tgt_len[b] : 0;
    const int bOff = b * CS;
    const int g = lane >> 2, qd = lane & 3;
#pragma unroll
    for (int nt = 0; nt < 8; nt++) {
        const int col = k0 + wn*64 + nt*8 + qd*2;
        const int r0  = q0 + wm*16 + g;
        const int r1  = r0 + 8;
        float* p0 = Sc + ((size_t)bh * CS + r0) * CS + col;
        float* p1 = Sc + ((size_t)bh * CS + r1) * CS + col;
        p0[0] = acc[nt][0] + score_bias<MODE>(r0, col,   hh, slen, tlen, relb, bacc, pmf, bOff, enc_layer);
        p0[1] = acc[nt][1] + score_bias<MODE>(r0, col+1, hh, slen, tlen, relb, bacc, pmf, bOff, enc_layer);
        p1[0] = acc[nt][2] + score_bias<MODE>(r1, col,   hh, slen, tlen, relb, bacc, pmf, bOff, enc_layer);
        p1[1] = acc[nt][3] + score_bias<MODE>(r1, col+1, hh, slen, tlen, relb, bacc, pmf, bOff, enc_layer);
    }
}

// ------------------------- tensor-core P @ V ------------------------------
// Per CTA: 64 q rows x 64 dk for one (b,h). K=512 in chunks of 32.
__global__ void __launch_bounds__(256) av_tc(
    const float* __restrict__ P, const float* __restrict__ V, float* __restrict__ O)
{
    constexpr int LDA = 40, LDB = 72;
    __shared__ __align__(16) __nv_bfloat16 Ah[64*LDA], Al[64*LDA];
    __shared__ __align__(16) __nv_bfloat16 Bh[32*LDB], Bl[32*LDB];

    const int bh = blockIdx.y, b = bh / CH, hh = bh % CH;
    const int q0 = blockIdx.x * 64;
    const int tid = threadIdx.x;
    const int lane = tid & 31, w = tid >> 5;
    const int wm = w & 3, wn = w >> 2;
    const int arow = tid >> 3, ac = (tid & 7) << 2;
    const int brow = tid >> 4, bc = (tid & 15) << 2;

    float4 pa[2];
    float4 pb[2];
    float acc[4][4];
#pragma unroll
    for (int i = 0; i < 4; i++) { acc[i][0]=acc[i][1]=acc[i][2]=acc[i][3]=0.f; }

    auto loadg = [&](int kt) {
#pragma unroll
        for (int it = 0; it < 2; it++)
            pa[it] = *(const float4*)(P + ((size_t)bh*CS + q0 + arow + it*32) * CS + kt*32 + ac);
#pragma unroll
        for (int it = 0; it < 2; it++)
            pb[it] = *(const float4*)(V + (size_t)(b*CS + kt*32 + brow + it*16) * CDM + hh*CDK + bc);
    };
    auto stores = [&]() {
#pragma unroll
        for (int it = 0; it < 2; it++) {
            int row = arow + it*32;
            splt(pa[it].x, Ah[row*LDA+ac+0], Al[row*LDA+ac+0]);
            splt(pa[it].y, Ah[row*LDA+ac+1], Al[row*LDA+ac+1]);
            splt(pa[it].z, Ah[row*LDA+ac+2], Al[row*LDA+ac+2]);
            splt(pa[it].w, Ah[row*LDA+ac+3], Al[row*LDA+ac+3]);
        }
#pragma unroll
        for (int it = 0; it < 2; it++) {
            int row = brow + it*16;
            splt(pb[it].x, Bh[row*LDB+bc+0], Bl[row*LDB+bc+0]);
            splt(pb[it].y, Bh[row*LDB+bc+1], Bl[row*LDB+bc+1]);
            splt(pb[it].z, Bh[row*LDB+bc+2], Bl[row*LDB+bc+2]);
            splt(pb[it].w, Bh[row*LDB+bc+3], Bl[row*LDB+bc+3]);
        }
    };

    loadg(0);
    stores();
    __syncthreads();

    for (int kt = 0; kt < CS/32; kt++) {
        const bool more = (kt + 1 < CS/32);
        if (more) loadg(kt + 1);
#pragma unroll
        for (int kh = 0; kh < 2; kh++) {
            unsigned ah[4], al[4];
            const int aoff = (wm*16 + (lane & 15)) * LDA + kh*16 + ((lane >> 4) << 3);
            ldsm4(ah, &Ah[aoff]);
            ldsm4(al, &Al[aoff]);
            unsigned bhf[8], blf[8];
#pragma unroll
            for (int t2 = 0; t2 < 2; t2++) {
                const int boff = (kh*16 + (lane & 15)) * LDB
                               + wn*32 + t2*16 + ((lane >> 4) << 3);
                ldsm4t(&bhf[t2*4], &Bh[boff]);
                ldsm4t(&blf[t2*4], &Bl[boff]);
            }
#pragma unroll
            for (int nt = 0; nt < 4; nt++) mma16816(acc[nt], ah, bhf[2*nt], bhf[2*nt+1]);
#pragma unroll
            for (int nt = 0; nt < 4; nt++) mma16816(acc[nt], ah, blf[2*nt], blf[2*nt+1]);
#pragma unroll
            for (int nt = 0; nt < 4; nt++) mma16816(acc[nt], al, bhf[2*nt], bhf[2*nt+1]);
        }
        __syncthreads();
        if (more) { stores(); __syncthreads(); }
    }

    const int g = lane >> 2, qd = lane & 3;
#pragma unroll
    for (int nt = 0; nt < 4; nt++) {
        const int col = hh*CDK + wn*32 + nt*8 + qd*2;
        const int r0  = b*CS + q0 + wm*16 + g;
        float* p0 = O + (size_t)r0 * CDM + col;
        float* p1 = p0 + (size_t)8 * CDM;
        p0[0] = acc[nt][0]; p0[1] = acc[nt][1];
        p1[0] = acc[nt][2]; p1[1] = acc[nt][3];
    }
}

// ------------------------- softmax over rows of length 512 ----------------
__global__ void __launch_bounds__(256) softmax_kernel(float* __restrict__ Sc)
{
    __shared__ float sh[8];
    float* row = Sc + (size_t)blockIdx.x * CS;
    const int t = threadIdx.x;
    float v0 = row[t], v1 = row[t + 256];
    float m = fmaxf(v0, v1);
#pragma unroll
    for (int o = 16; o; o >>= 1) m = fmaxf(m, __shfl_xor_sync(0xffffffffu, m, o));
    if ((t & 31) == 0) sh[t >> 5] = m;
    __syncthreads();
    float bm = sh[t & 7];
#pragma unroll
    for (int o = 4; o; o >>= 1) bm = fmaxf(bm, __shfl_xor_sync(0xffffffffu, bm, o));
    float e0 = expf(v0 - bm), e1 = expf(v1 - bm);
    float s = e0 + e1;
#pragma unroll
    for (int o = 16; o; o >>= 1) s += __shfl_xor_sync(0xffffffffu, s, o);
    __syncthreads();
    if ((t & 31) == 0) sh[t >> 5] = s;
    __syncthreads();
    float ts = sh[t & 7];
#pragma unroll
    for (int o = 4; o; o >>= 1) ts += __shfl_xor_sync(0xffffffffu, ts, o);
    float inv = 1.f / ts;
    row[t] = e0 * inv; row[t + 256] = e1 * inv;
}

// ------------------------- RMSNorm (T5) -----------------------------------
__global__ void __launch_bounds__(256) rms_kernel(
    const float* __restrict__ x, const float* __restrict__ w,
    float* __restrict__ out, float scale)
{
    __shared__ float sh[8];
    const int row = blockIdx.x, t = threadIdx.x;
    const float* xr = x + (size_t)row * CDM;
    float v0 = xr[t], v1 = xr[t+256], v2 = xr[t+512];
    float s = v0*v0 + v1*v1 + v2*v2;
#pragma unroll
    for (int o = 16; o; o >>= 1) s += __shfl_xor_sync(0xffffffffu, s, o);
    if ((t & 31) == 0) sh[t >> 5] = s;
    __syncthreads();
    float ts = sh[t & 7];
#pragma unroll
    for (int o = 4; o; o >>= 1) ts += __shfl_xor_sync(0xffffffffu, ts, o);
    float inv = rsqrtf(ts * (1.0f/CDM) + 1e-6f) * scale;
    float* orow = out + (size_t)row * CDM;
    orow[t]     = v0 * inv * w[t];
    orow[t+256] = v1 * inv * w[t+256];
    orow[t+512] = v2 * inv * w[t+512];
}

// ------------------------- elementwise helpers ----------------------------
__global__ void __launch_bounds__(256) embed_gather(
    const float* __restrict__ embed, const int* __restrict__ tok,
    float* __restrict__ out)
{
    int idx = blockIdx.x * 256 + threadIdx.x;
    int r = idx / CDM, c = idx - r * CDM;
    out[idx] = embed[(size_t)tok[r] * CDM + c];
}

__global__ void zero_ch0(float* __restrict__ x)
{
    int r = blockIdx.x * 256 + threadIdx.x;
    if (r < NROWS) x[(size_t)r * CDM] = 0.f;
}

__global__ void init_bacc()
{
    int i = blockIdx.x * 256 + threadIdx.x;
    if (i < CB*CS) g_bacc[i] = 0.f;
}

__global__ void copy_k(const float* __restrict__ src, float* __restrict__ dst)
{
    int i = blockIdx.x * 256 + threadIdx.x;
    dst[i] = src[i];
}

// ------------------------- prune gate -------------------------------------
__global__ void __launch_bounds__(512) gate_kernel(
    const float* __restrict__ x, const float* __restrict__ gumbel,
    const int* __restrict__ src_len, const int* __restrict__ keep,
    float* __restrict__ out_pm, float* __restrict__ out_pp, int layer)
{
    const int b = blockIdx.x, s = threadIdx.x;
    float x0 = x[(size_t)(b*CS + s) * CDM];
    float z = (x0 + gumbel[(b*CL + layer) * CS + s] + 3.0f) * 2.0f;
    float ls = (z >= 0.f) ? -log1pf(expf(-z)) : (z - log1pf(expf(z)));
    float pm = ls + ((layer > 0) ? g_pm[b*CS + s] : 0.f);
    if (s == keep[b]) pm = 0.f;
    g_pm[b*CS + s] = pm;
    g_bacc[b*CS + s] += pm;
    out_pm[(b*CL + layer) * CS + s] = pm;
    out_pp[(b*CL + layer) * CS + s] = expf(pm * 0.125f) * ((s < src_len[b]) ? 1.f : 0.f);
}

// ------------------------- host orchestration -----------------------------
extern "C" void kernel_launch(void* const* d_in, const int* in_sizes, int n_in,
                              void* d_out, int out_size)
{
    const float* embed      = (const float*)d_in[0];
    const float* enc_ln     = (const float*)d_in[1];
    const float* enc_attn_w = (const float*)d_in[2];
    const float* enc_wi     = (const float*)d_in[3];
    const float* enc_wo     = (const float*)d_in[4];
    const float* enc_relb   = (const float*)d_in[5];
    const float* enc_fln    = (const float*)d_in[6];
    const float* dec_ln     = (const float*)d_in[7];
    const float* dec_self_w = (const float*)d_in[8];
    const float* dec_cross_w= (const float*)d_in[9];
    const float* dec_wi     = (const float*)d_in[10];
    const float* dec_wo     = (const float*)d_in[11];
    const float* dec_relb   = (const float*)d_in[12];
    const float* dec_fln    = (const float*)d_in[13];
    const float* gumbel     = (const float*)d_in[14];
    const int*   src_tok    = (const int*)d_in[15];
    const int*   src_len    = (const int*)d_in[16];
    const int*   tgt_tok    = (const int*)d_in[17];
    const int*   tgt_len    = (const int*)d_in[18];
    const int*   keep       = (const int*)d_in[19];

    float* out = (float*)d_out;
    float* out_mem = out;
    float* out_pm  = out + (size_t)CB*CS*CDM;
    float* out_pp  = out_pm + (size_t)CB*CL*CS;
    float* out_log = out_pp + (size_t)CB*CL*CS;

    float *x, *h, *qkv, *o, *mem, *ff, *sc, *bacc, *pm;
    cudaGetSymbolAddress((void**)&x,   g_x);
    cudaGetSymbolAddress((void**)&h,   g_h);
    cudaGetSymbolAddress((void**)&qkv, g_qkv);
    cudaGetSymbolAddress((void**)&o,   g_o);
    cudaGetSymbolAddress((void**)&mem, g_mem);
    cudaGetSymbolAddress((void**)&ff,  g_ff);
    cudaGetSymbolAddress((void**)&sc,  g_sc);
    cudaGetSymbolAddress((void**)&bacc,g_bacc);
    cudaGetSymbolAddress((void**)&pm,  g_pm);

    float* q = qkv;
    float* k = qkv + (size_t)NROWS*CDM;
    float* v = qkv + (size_t)2*NROWS*CDM;
    const long QS = (long)NROWS*CDM;
    const long WS = (long)CDM*CDM;

    const dim3 gQKV(CDM/64, NROWS/64, 3);
    const dim3 gPrj(CDM/64, NROWS/64);
    const dim3 gWi (CDFF/128, NROWS/64);
    const dim3 gLg (CV/128, NROWS/64);
    const dim3 gSc(CS/128, CS/64, CB*CH);
    const dim3 gAv(CS/64, CB*CH);
    const int  nSoft = CB*CH*CS;
    const float inv_sqrt_dm = 0.03608439182435161f;

    init_bacc<<<4, 256>>>();
    embed_gather<<<NROWS*CDM/256, 256>>>(embed, src_tok, x);

    // ---------------- encoder ----------------
    for (int i = 0; i < CL; i++) {
        const float* W = enc_attn_w + (size_t)i*4*CDM*CDM;
        zero_ch0<<<4, 256>>>(x);
        rms_kernel<<<NROWS, 256>>>(x, enc_ln + (size_t)(i*2+0)*CDM, h, 1.f);
        gemm_tc<64,false,false,false,true><<<gQKV, 256>>>(
            h, h, W, WS, qkv, QS, NROWS, CDM, CDM);
        scores_tc<0><<<gSc, 256>>>(q, k, sc, enc_relb, src_len, tgt_len, bacc, pm, i);
        softmax_kernel<<<nSoft, 256>>>(sc);
        av_tc<<<gAv, 256>>>(sc, v, o);
        gemm_tc<64,false,true,false,false><<<gPrj, 256>>>(
            o, o, W + 3*WS, 0, x, 0, NROWS, CDM, CDM);
        rms_kernel<<<NROWS, 256>>>(x, enc_ln + (size_t)(i*2+1)*CDM, h, 1.f);
        gemm_tc<128,false,false,true,false><<<gWi, 256>>>(
            h, h, enc_wi + (size_t)i*CDM*CDFF, 0, ff, 0, NROWS, CDFF, CDM);
        gemm_tc<64,false,true,false,false><<<gPrj, 256>>>(
            ff, ff, enc_wo + (size_t)i*CDFF*CDM, 0, x, 0, NROWS, CDM, CDFF);
        gate_kernel<<<CB, 512>>>(x, gumbel, src_len, keep, out_pm, out_pp, i);
    }
    rms_kernel<<<NROWS, 256>>>(x, enc_fln, mem, 1.f);
    copy_k<<<NROWS*CDM/256, 256>>>(mem, out_mem);

    // ---------------- decoder ----------------
    embed_gather<<<NROWS*CDM/256, 256>>>(embed, tgt_tok, x);
    for (int i = 0; i < CL; i++) {
        const float* Ws = dec_self_w  + (size_t)i*4*CDM*CDM;
        const float* Wc = dec_cross_w + (size_t)i*4*CDM*CDM;
        // self attention
        rms_kernel<<<NROWS, 256>>>(x, dec_ln + (size_t)(i*3+0)*CDM, h, 1.f);
        gemm_tc<64,false,false,false,true><<<gQKV, 256>>>(
            h, h, Ws, WS, qkv, QS, NROWS, CDM, CDM);
        scores_tc<1><<<gSc, 256>>>(q, k, sc, dec_relb, src_len, tgt_len, bacc, pm, 0);
        softmax_kernel<<<nSoft, 256>>>(sc);
        av_tc<<<gAv, 256>>>(sc, v, o);
        gemm_tc<64,false,true,false,false><<<gPrj, 256>>>(
            o, o, Ws + 3*WS, 0, x, 0, NROWS, CDM, CDM);
        // cross attention (q from h, k/v from mem)
        rms_kernel<<<NROWS, 256>>>(x, dec_ln + (size_t)(i*3+1)*CDM, h, 1.f);
        gemm_tc<64,false,false,false,true><<<gQKV, 256>>>(
            h, mem, Wc, WS, qkv, QS, NROWS, CDM, CDM);
        scores_tc<2><<<gSc, 256>>>(q, k, sc, dec_relb, src_len, tgt_len, bacc, pm, 0);
        softmax_kernel<<<nSoft, 256>>>(sc);
        av_tc<<<gAv, 256>>>(sc, v, o);
        gemm_tc<64,false,true,false,false><<<gPrj, 256>>>(
            o, o, Wc + 3*WS, 0, x, 0, NROWS, CDM, CDM);
        // ffn
        rms_kernel<<<NROWS, 256>>>(x, dec_ln + (size_t)(i*3+2)*CDM, h, 1.f);
        gemm_tc<128,false,false,true,false><<<gWi, 256>>>(
            h, h, dec_wi + (size_t)i*CDM*CDFF, 0, ff, 0, NROWS, CDFF, CDM);
        gemm_tc<64,false,true,false,false><<<gPrj, 256>>>(
            ff, ff, dec_wo + (size_t)i*CDFF*CDM, 0, x, 0, NROWS, CDM, CDFF);
    }
    rms_kernel<<<NROWS, 256>>>(x, dec_fln, h, inv_sqrt_dm);
    gemm_tc<128,true,false,false,false><<<gLg, 256>>>(
        h, h, embed, 0, out_log, 0, NROWS, CV, CDM);
}